// round 1
// baseline (speedup 1.0000x reference)
#include <cuda_runtime.h>
#include <cuda_bf16.h>
#include <cstdint>

// Problem constants (from reference setup_inputs)
#define BB 32
#define CC 2
#define HH 480
#define WW 864
#define HW (HH * WW)
#define KHALF 7          // 15x15 kernel half-width
#define CHUNK 48         // rows per thread in vertical pass
#define NCHUNK (HH / CHUNK)   // 10
#define BLKW 288         // 864 = 3 * 288, multiple of 32

// Scratch: per-pixel horizontal code. bit0 = window-of-15-cols contains np_label==0,
// bit1 = contains np_label!=0(=255). OOB columns contribute 0 (neutral, matches
// reduce_window identity padding).
__device__ unsigned char g_hcode[BB * HW];
__device__ double g_sum;
__device__ int    g_cnt;

__global__ void bl_init_kernel() {
    g_sum = 0.0;
    g_cnt = 0;
}

// ---------------------------------------------------------------------------
// Pass A: horizontal boolean dilation of the two masks, per row.
// grid = (3, H, B), block = 288. Each block owns 288 contiguous columns of one
// row; loads 288+14 label codes into smem, each thread ORs its 15-wide window.
// ---------------------------------------------------------------------------
__global__ __launch_bounds__(BLKW) void bl_hpass_kernel(const int* __restrict__ labels) {
    __shared__ unsigned char s[BLKW + 2 * KHALF];

    const int b = blockIdx.z;
    const int h = blockIdx.y;
    const int wbase = blockIdx.x * BLKW;
    const int* __restrict__ row = labels + (b * HH + h) * WW;

    for (int i = threadIdx.x; i < BLKW + 2 * KHALF; i += BLKW) {
        int w = wbase - KHALF + i;
        unsigned char c = 0;
        if (w >= 0 && w < WW) {
            int l = __ldg(row + w);
            // np_label = (l==IGNORE) ? 0 : l*255 ; code: bit0 = (np==0), bit1 = (np!=0)
            int np = (l == 255) ? 0 : l * 255;
            c = (np == 0) ? 1u : 2u;
        }
        s[i] = c;
    }
    __syncthreads();

    unsigned char acc = 0;
#pragma unroll
    for (int k = 0; k < 2 * KHALF + 1; k++) acc |= s[threadIdx.x + k];

    g_hcode[(b * HH + h) * WW + wbase + threadIdx.x] = acc;
}

// ---------------------------------------------------------------------------
// Pass B: vertical boolean dilation (bit-packed shift register) fused with the
// NLL gather + reduction.
// grid = (3, B, NCHUNK), block = 288. Thread owns one (b, w) column for CHUNK
// rows. State u32 holds the last 15 row-codes, 2 bits each:
//   st = ((st << 2) | code) & 0x3FFFFFFF
//   boundary  <=>  (st & 0x15555555) && (st & 0x2AAAAAAA)
// valid pixel <=> boundary && label != 255; picked = logits[b, label, h, w].
// Both channel values are loaded unconditionally (fully coalesced; random
// labels touch both cache lines anyway) and selected.
// ---------------------------------------------------------------------------
__global__ __launch_bounds__(BLKW) void bl_vpass_kernel(const float* __restrict__ logits,
                                                        const int*   __restrict__ labels) {
    const int w  = blockIdx.x * BLKW + threadIdx.x;
    const int b  = blockIdx.y;
    const int h0 = blockIdx.z * CHUNK;

    const unsigned char* __restrict__ col = g_hcode + b * HW + w;
    const int*   __restrict__ lab = labels + b * HW + w;
    const float* __restrict__ lg0 = logits + b * CC * HW + w;
    const float* __restrict__ lg1 = lg0 + HW;

    // Warm up: push rows [h0-7, h0+6]  (14 codes). OOB rows contribute 0.
    unsigned st = 0;
#pragma unroll
    for (int i = 0; i < 2 * KHALF; i++) {
        int hh = h0 - KHALF + i;          // max h0 = 432 -> hh <= 438 < 480
        unsigned c = (hh >= 0) ? (unsigned)col[hh * WW] : 0u;
        st = (st << 2) | c;
    }

    float lsum = 0.0f;
    int   lcnt = 0;

#pragma unroll 4
    for (int h = h0; h < h0 + CHUNK; h++) {
        int hh = h + KHALF;
        unsigned c = (hh < HH) ? (unsigned)col[hh * WW] : 0u;
        st = ((st << 2) | c) & 0x3FFFFFFFu;

        int   l  = lab[h * WW];
        float v0 = lg0[h * WW];
        float v1 = lg1[h * WW];

        bool boundary = (st & 0x15555555u) != 0u && (st & 0x2AAAAAAAu) != 0u;
        if (boundary && l != 255) {
            lsum += (l != 0) ? v1 : v0;
            lcnt += 1;
        }
    }

    // Reduce within warp
#pragma unroll
    for (int o = 16; o > 0; o >>= 1) {
        lsum += __shfl_down_sync(0xFFFFFFFFu, lsum, o);
        lcnt += __shfl_down_sync(0xFFFFFFFFu, lcnt, o);
    }

    __shared__ float ws[BLKW / 32];
    __shared__ int   wc[BLKW / 32];
    const int wid = threadIdx.x >> 5;
    const int lid = threadIdx.x & 31;
    if (lid == 0) { ws[wid] = lsum; wc[wid] = lcnt; }
    __syncthreads();

    if (threadIdx.x == 0) {
        double bs = 0.0;
        int    bc = 0;
#pragma unroll
        for (int i = 0; i < BLKW / 32; i++) { bs += (double)ws[i]; bc += wc[i]; }
        atomicAdd(&g_sum, bs);
        atomicAdd(&g_cnt, bc);
    }
}

__global__ void bl_finalize_kernel(float* __restrict__ out) {
    int n = g_cnt > 0 ? g_cnt : 1;
    out[0] = (float)(-g_sum / (double)n);
}

extern "C" void kernel_launch(void* const* d_in, const int* in_sizes, int n_in,
                              void* d_out, int out_size) {
    const float* logits = (const float*)d_in[0];
    const int*   labels = (const int*)d_in[1];
    float*       out    = (float*)d_out;

    bl_init_kernel<<<1, 1>>>();
    bl_hpass_kernel<<<dim3(WW / BLKW, HH, BB), BLKW>>>(labels);
    bl_vpass_kernel<<<dim3(WW / BLKW, BB, NCHUNK), BLKW>>>(logits, labels);
    bl_finalize_kernel<<<1, 1>>>(out);
}

// round 2
// speedup vs baseline: 1.1165x; 1.1165x over previous
#include <cuda_runtime.h>
#include <cuda_bf16.h>
#include <cstdint>

// Problem constants (from reference setup_inputs)
#define BB 32
#define HH 480
#define WW 864
#define HW (HH * WW)
#define KHALF 7
#define CHUNK 24
#define NCH (HH / CHUNK)        // 20
#define TPB 224                 // 7 warps; 216 active (216*4 = 864 cols)
#define ACT 216
#define NBLK (NCH * BB)         // 640 vpass blocks

// hcode byte per pixel:
//   bits[0:2] : 15-col-window content: bit0 = contains np_label==0 (cls0 or ignore),
//               bit1 = contains np_label==255 (cls1). OOB cols contribute 0 (neutral).
//   bits[2:4] : own label class: 1 = cls0, 2 = cls1, 0 = ignore.
__device__ unsigned char g_hcode[BB * HW];
__device__ double   g_psum[NBLK];
__device__ int      g_pcnt[NBLK];
__device__ unsigned g_ticket = 0;   // reset by last block every run

// ---------------------------------------------------------------------------
// Pass A: per-row horizontal dilation, 4 outputs/thread via word-masked ORs.
// grid = (HH, BB), block = TPB.
// ---------------------------------------------------------------------------
__global__ __launch_bounds__(TPB) void bl_hpass(const int* __restrict__ labels) {
    __shared__ unsigned s_w[224];               // 896 bytes; s[i] = code of col (i-7)
    unsigned char* s = (unsigned char*)s_w;

    const int b = blockIdx.y;
    const int h = blockIdx.x;
    const int* __restrict__ row = labels + (b * HH + h) * WW;

    for (int i = threadIdx.x; i < 896; i += TPB) {
        unsigned char c = 0;
        int w = i - KHALF;
        if (w >= 0 && w < WW) {
            int l = __ldg(row + w);
            c = (l == 255) ? 0x01 : (l ? 0x0A : 0x05);
        }
        s[i] = c;
    }
    __syncthreads();

    const int t = threadIdx.x;
    if (t < ACT) {
        const unsigned* sw = s_w + t;           // word t = bytes [4t, 4t+4)
        unsigned W0 = sw[0], W1 = sw[1], W2 = sw[2], W3 = sw[3], W4 = sw[4];
        unsigned M0 = W0 & 0x03030303u, M1 = W1 & 0x03030303u,
                 M2 = W2 & 0x03030303u, M3 = W3 & 0x03030303u,
                 M4 = W4 & 0x03030303u;
        unsigned base = M1 | M2;
        // window for output col c = OR of s-bytes [c, c+14]
        unsigned w0 = M0 | base | (M3 & 0x00FFFFFFu);
        unsigned w1 = (M0 & 0xFFFFFF00u) | base | M3;
        unsigned w2 = (M0 & 0xFFFF0000u) | base | M3 | (M4 & 0x000000FFu);
        unsigned w3 = (M0 & 0xFF000000u) | base | M3 | (M4 & 0x0000FFFFu);
        w0 |= w0 >> 16; w0 |= w0 >> 8;
        w1 |= w1 >> 16; w1 |= w1 >> 8;
        w2 |= w2 >> 16; w2 |= w2 >> 8;
        w3 |= w3 >> 16; w3 |= w3 >> 8;
        unsigned o0 = (w0 & 3u) | ((W1 >> 24) & 0x0Cu);   // own = s[c+7]
        unsigned o1 = (w1 & 3u) | ( W2        & 0x0Cu);
        unsigned o2 = (w2 & 3u) | ((W2 >> 8)  & 0x0Cu);
        unsigned o3 = (w3 & 3u) | ((W2 >> 16) & 0x0Cu);
        *(unsigned*)(g_hcode + (b * HH + h) * WW + 4 * t) =
            o0 | (o1 << 8) | (o2 << 16) | (o3 << 24);
    }
}

// ---------------------------------------------------------------------------
// Pass B: vertical dilation (packed 2-bit shift registers, 4 cols/thread),
// fused gather + reduction + last-block finalize.
// grid = (NCH, BB), block = TPB.
// ---------------------------------------------------------------------------
__global__ __launch_bounds__(TPB) void bl_vpass(const float* __restrict__ logits,
                                                float* __restrict__ out) {
    const int chunk = blockIdx.x;
    const int b     = blockIdx.y;
    const int h0    = chunk * CHUNK;
    const int t     = threadIdx.x;

    float lsum = 0.0f;
    int   lcnt = 0;

    if (t < ACT) {
        const int c0 = 4 * t;
        const unsigned char* __restrict__ col = g_hcode + b * HW + c0;
        const float* __restrict__ lg0 = logits + (size_t)b * 2 * HW + c0;
        const float* __restrict__ lg1 = lg0 + HW;

        unsigned s0 = 0, s1 = 0, s2 = 0, s3 = 0;
        unsigned q[8];                      // ring of raw hcode words (own-label source)
#pragma unroll
        for (int i = 0; i < 2 * KHALF; i++) {
            int hh = h0 - KHALF + i;        // hh <= h0+6 <= 462 < HH always
            unsigned p = (hh >= 0) ? *(const unsigned*)(col + hh * WW) : 0u;
            s0 = (s0 << 2) | ( p        & 3u);
            s1 = (s1 << 2) | ((p >>  8) & 3u);
            s2 = (s2 << 2) | ((p >> 16) & 3u);
            s3 = (s3 << 2) | ((p >> 24) & 3u);
            if (hh >= h0) q[hh & 7] = p;    // rows h0 .. h0+6
        }

#pragma unroll
        for (int h = h0; h < h0 + CHUNK; h++) {
            const int hh = h + KHALF;
            unsigned p = (hh < HH) ? *(const unsigned*)(col + hh * WW) : 0u;
            float4 v0 = *(const float4*)(lg0 + h * WW);
            float4 v1 = *(const float4*)(lg1 + h * WW);

            unsigned own = q[h & 7];
            q[hh & 7] = p;

            s0 = ((s0 << 2) | ( p        & 3u)) & 0x3FFFFFFFu;
            s1 = ((s1 << 2) | ((p >>  8) & 3u)) & 0x3FFFFFFFu;
            s2 = ((s2 << 2) | ((p >> 16) & 3u)) & 0x3FFFFFFFu;
            s3 = ((s3 << 2) | ((p >> 24) & 3u)) & 0x3FFFFFFFu;

            {
                unsigned ob = (own >> 2) & 3u;
                if ((s0 & 0x15555555u) && (s0 & 0x2AAAAAAAu) && ob) {
                    lsum += (ob & 2u) ? v1.x : v0.x; lcnt++;
                }
            }
            {
                unsigned ob = (own >> 10) & 3u;
                if ((s1 & 0x15555555u) && (s1 & 0x2AAAAAAAu) && ob) {
                    lsum += (ob & 2u) ? v1.y : v0.y; lcnt++;
                }
            }
            {
                unsigned ob = (own >> 18) & 3u;
                if ((s2 & 0x15555555u) && (s2 & 0x2AAAAAAAu) && ob) {
                    lsum += (ob & 2u) ? v1.z : v0.z; lcnt++;
                }
            }
            {
                unsigned ob = (own >> 26) & 3u;
                if ((s3 & 0x15555555u) && (s3 & 0x2AAAAAAAu) && ob) {
                    lsum += (ob & 2u) ? v1.w : v0.w; lcnt++;
                }
            }
        }
    }

    // Block reduction
#pragma unroll
    for (int o = 16; o > 0; o >>= 1) {
        lsum += __shfl_down_sync(0xFFFFFFFFu, lsum, o);
        lcnt += __shfl_down_sync(0xFFFFFFFFu, lcnt, o);
    }
    __shared__ float ws[TPB / 32];
    __shared__ int   wc[TPB / 32];
    __shared__ bool  s_last;
    const int wid = t >> 5, lid = t & 31;
    if (lid == 0) { ws[wid] = lsum; wc[wid] = lcnt; }
    __syncthreads();

    const int bid = b * NCH + chunk;
    if (t == 0) {
        double bs = 0.0; int bc = 0;
#pragma unroll
        for (int i = 0; i < TPB / 32; i++) { bs += (double)ws[i]; bc += wc[i]; }
        g_psum[bid] = bs;
        g_pcnt[bid] = bc;
        __threadfence();
        unsigned r = atomicAdd(&g_ticket, 1u);
        s_last = (r == NBLK - 1);
    }
    __syncthreads();

    if (s_last) {
        // Final reduction over all block partials (only the last block gets here)
        double ds = 0.0; long long dc = 0;
        for (int i = t; i < NBLK; i += TPB) { ds += g_psum[i]; dc += g_pcnt[i]; }
#pragma unroll
        for (int o = 16; o > 0; o >>= 1) {
            ds += __shfl_down_sync(0xFFFFFFFFu, ds, o);
            dc += __shfl_down_sync(0xFFFFFFFFu, dc, o);
        }
        __shared__ double fs[TPB / 32];
        __shared__ long long fc[TPB / 32];
        if (lid == 0) { fs[wid] = ds; fc[wid] = dc; }
        __syncthreads();
        if (t == 0) {
            double S = 0.0; long long C = 0;
#pragma unroll
            for (int i = 0; i < TPB / 32; i++) { S += fs[i]; C += fc[i]; }
            if (C < 1) C = 1;
            out[0] = (float)(-S / (double)C);
            g_ticket = 0;                   // reset for next graph replay
        }
    }
}

extern "C" void kernel_launch(void* const* d_in, const int* in_sizes, int n_in,
                              void* d_out, int out_size) {
    const float* logits = (const float*)d_in[0];
    const int*   labels = (const int*)d_in[1];
    float*       out    = (float*)d_out;

    bl_hpass<<<dim3(HH, BB), TPB>>>(labels);
    bl_vpass<<<dim3(NCH, BB), TPB>>>(logits, out);
}

// round 4
// speedup vs baseline: 1.4375x; 1.2875x over previous
#include <cuda_runtime.h>
#include <cuda_bf16.h>
#include <cstdint>

// Problem constants
#define BB 32
#define HH 480
#define WW 864
#define HW (HH * WW)
#define KHALF 7
#define CHUNK 16
#define ROWS (CHUNK + 2 * KHALF)   // 30 smem rows per block
#define NCH (HH / CHUNK)           // 30
#define TPB 224                    // 7 warps
#define ACT 216                    // 216 * 4 = 864 columns
#define SWORDS 224                 // words per smem row (896 B stride)
#define NBLK (NCH * BB)            // 960

__device__ double   g_psum[NBLK];
__device__ int      g_pcnt[NBLK];
__device__ unsigned g_ticket = 0;

// Smem layout: per row, byte (c+8) holds the 1-byte code of column c.
//   code bits[0:2]: bit0 = np_label==0 (l==0 or l==255), bit1 = np_label==255 (l==1)
//   code bits[2:4]: own class (1 = cls0, 2 = cls1, 0 = ignore)
// Thread t (cols 4t..4t+3) reads words t..t+4 of a row for the 15-col fold;
// its own-label word is word t+2 of the center row.

__global__ __launch_bounds__(TPB, 6) void bl_fused(const float* __restrict__ logits,
                                                   const int*   __restrict__ labels,
                                                   float* __restrict__ out) {
    __shared__ unsigned s_w[ROWS * SWORDS];    // 26,880 B

    const int chunk = blockIdx.x;
    const int b     = blockIdx.y;
    const int h0    = chunk * CHUNK;
    const int t     = threadIdx.x;

    // Zero (halos + OOB rows rely on this)
    for (int i = t; i < ROWS * SWORDS; i += TPB) s_w[i] = 0u;
    __syncthreads();

    // Fill: labels -> packed code words (int4-coalesced)
    for (int u = t; u < ROWS * 216; u += TPB) {
        const int r  = u / 216;
        const int j  = u - r * 216;
        const int gh = h0 - KHALF + r;
        if (gh >= 0 && gh < HH) {
            const int4 l4 = *(const int4*)(labels + ((size_t)b * HH + gh) * WW + 4 * j);
            unsigned c0 = (l4.x == 255) ? 1u : (l4.x ? 0x0Au : 0x05u);
            unsigned c1 = (l4.y == 255) ? 1u : (l4.y ? 0x0Au : 0x05u);
            unsigned c2 = (l4.z == 255) ? 1u : (l4.z ? 0x0Au : 0x05u);
            unsigned c3 = (l4.w == 255) ? 1u : (l4.w ? 0x0Au : 0x05u);
            s_w[r * SWORDS + 2 + j] = c0 | (c1 << 8) | (c2 << 16) | (c3 << 24);
        }
    }
    __syncthreads();

    float lsum = 0.0f;
    int   lcnt = 0;

    if (t < ACT) {
        unsigned s0 = 0, s1 = 0, s2 = 0, s3 = 0;

        // Warmup: fold rows r = 0..13 (global h0-7 .. h0+6)
#pragma unroll
        for (int r = 0; r < 2 * KHALF; r++) {
            const unsigned* sw = s_w + r * SWORDS + t;
            unsigned W0 = sw[0], W1 = sw[1], W2 = sw[2], W3 = sw[3], W4 = sw[4];
            unsigned M0 = W0 & 0x03030303u, M4 = W4 & 0x03030303u;
            unsigned base = (W1 | W2 | W3) & 0x03030303u;
            unsigned w0 = (M0 & 0xFFFFFF00u) | base;
            unsigned w1 = (M0 & 0xFFFF0000u) | base | (M4 & 0x000000FFu);
            unsigned w2 = (M0 & 0xFF000000u) | base | (M4 & 0x0000FFFFu);
            unsigned w3 =                      base | (M4 & 0x00FFFFFFu);
            w0 |= w0 >> 16; w0 |= w0 >> 8;
            w1 |= w1 >> 16; w1 |= w1 >> 8;
            w2 |= w2 >> 16; w2 |= w2 >> 8;
            w3 |= w3 >> 16; w3 |= w3 >> 8;
            s0 = (s0 << 2) | (w0 & 3u);
            s1 = (s1 << 2) | (w1 & 3u);
            s2 = (s2 << 2) | (w2 & 3u);
            s3 = (s3 << 2) | (w3 & 3u);
        }

        const float* __restrict__ lg0 = logits + (size_t)b * 2 * HW + 4 * t;
        const float* __restrict__ lg1 = lg0 + HW;

#pragma unroll 8
        for (int i = 0; i < CHUNK; i++) {
            const int r = i + 2 * KHALF;            // fold row h0 + i + 7
            const unsigned* sw = s_w + r * SWORDS + t;
            unsigned W0 = sw[0], W1 = sw[1], W2 = sw[2], W3 = sw[3], W4 = sw[4];
            const unsigned wC = s_w[(i + KHALF) * SWORDS + t + 2];  // center (own) row h0+i
            const float4 v0 = *(const float4*)(lg0 + (h0 + i) * WW);
            const float4 v1 = *(const float4*)(lg1 + (h0 + i) * WW);

            unsigned M0 = W0 & 0x03030303u, M4 = W4 & 0x03030303u;
            unsigned base = (W1 | W2 | W3) & 0x03030303u;
            unsigned w0 = (M0 & 0xFFFFFF00u) | base;
            unsigned w1 = (M0 & 0xFFFF0000u) | base | (M4 & 0x000000FFu);
            unsigned w2 = (M0 & 0xFF000000u) | base | (M4 & 0x0000FFFFu);
            unsigned w3 =                      base | (M4 & 0x00FFFFFFu);
            w0 |= w0 >> 16; w0 |= w0 >> 8;
            w1 |= w1 >> 16; w1 |= w1 >> 8;
            w2 |= w2 >> 16; w2 |= w2 >> 8;
            w3 |= w3 >> 16; w3 |= w3 >> 8;

            s0 = ((s0 << 2) | (w0 & 3u)) & 0x3FFFFFFFu;
            s1 = ((s1 << 2) | (w1 & 3u)) & 0x3FFFFFFFu;
            s2 = ((s2 << 2) | (w2 & 3u)) & 0x3FFFFFFFu;
            s3 = ((s3 << 2) | (w3 & 3u)) & 0x3FFFFFFFu;

            {
                unsigned ob = (wC >> 2) & 3u;
                if ((s0 & 0x15555555u) && (s0 & 0x2AAAAAAAu) && ob) {
                    lsum += (ob & 2u) ? v1.x : v0.x; lcnt++;
                }
            }
            {
                unsigned ob = (wC >> 10) & 3u;
                if ((s1 & 0x15555555u) && (s1 & 0x2AAAAAAAu) && ob) {
                    lsum += (ob & 2u) ? v1.y : v0.y; lcnt++;
                }
            }
            {
                unsigned ob = (wC >> 18) & 3u;
                if ((s2 & 0x15555555u) && (s2 & 0x2AAAAAAAu) && ob) {
                    lsum += (ob & 2u) ? v1.z : v0.z; lcnt++;
                }
            }
            {
                unsigned ob = (wC >> 26) & 3u;
                if ((s3 & 0x15555555u) && (s3 & 0x2AAAAAAAu) && ob) {
                    lsum += (ob & 2u) ? v1.w : v0.w; lcnt++;
                }
            }
        }
    }

    // Block reduction
#pragma unroll
    for (int o = 16; o > 0; o >>= 1) {
        lsum += __shfl_down_sync(0xFFFFFFFFu, lsum, o);
        lcnt += __shfl_down_sync(0xFFFFFFFFu, lcnt, o);
    }
    __shared__ float ws[TPB / 32];
    __shared__ int   wc[TPB / 32];
    __shared__ bool  s_last;
    const int wid = t >> 5, lid = t & 31;
    if (lid == 0) { ws[wid] = lsum; wc[wid] = lcnt; }
    __syncthreads();

    const int bid = blockIdx.y * NCH + blockIdx.x;
    if (t == 0) {
        double bs = 0.0; int bc = 0;
#pragma unroll
        for (int i = 0; i < TPB / 32; i++) { bs += (double)ws[i]; bc += wc[i]; }
        g_psum[bid] = bs;
        g_pcnt[bid] = bc;
        __threadfence();
        unsigned r = atomicAdd(&g_ticket, 1u);
        s_last = (r == NBLK - 1);
    }
    __syncthreads();

    if (s_last) {
        double ds = 0.0; long long dc = 0;
        for (int i = t; i < NBLK; i += TPB) { ds += g_psum[i]; dc += g_pcnt[i]; }
#pragma unroll
        for (int o = 16; o > 0; o >>= 1) {
            ds += __shfl_down_sync(0xFFFFFFFFu, ds, o);
            dc += __shfl_down_sync(0xFFFFFFFFu, dc, o);
        }
        __shared__ double    fs[TPB / 32];
        __shared__ long long fc[TPB / 32];
        if (lid == 0) { fs[wid] = ds; fc[wid] = dc; }
        __syncthreads();
        if (t == 0) {
            double S = 0.0; long long C = 0;
#pragma unroll
            for (int i = 0; i < TPB / 32; i++) { S += fs[i]; C += fc[i]; }
            if (C < 1) C = 1;
            out[0] = (float)(-S / (double)C);
            g_ticket = 0;                    // reset for next graph replay
        }
    }
}

extern "C" void kernel_launch(void* const* d_in, const int* in_sizes, int n_in,
                              void* d_out, int out_size) {
    const float* logits = (const float*)d_in[0];
    const int*   labels = (const int*)d_in[1];
    float*       out    = (float*)d_out;

    bl_fused<<<dim3(NCH, BB), TPB>>>(logits, labels, out);
}